// round 2
// baseline (speedup 1.0000x reference)
#include <cuda_runtime.h>
#include <cuda_bf16.h>
#include <stdint.h>

// Problem constants: B=8, S=2048 -> M=16384 rows; LATENT = EDIM = 512; NE = 8192.
#define MROWS 16384
#define KDIM  512
#define NEMB  8192
#define CAND_CAP 64

// ---------------- scratch (static __device__ arrays; no allocs) -------------
__device__ float                        g_zf[(size_t)MROWS * KDIM];
__device__ __align__(16) __nv_bfloat16  g_zfb[(size_t)MROWS * KDIM];
__device__ float                        g_embn[(size_t)NEMB * KDIM];
__device__ __align__(16) __nv_bfloat16  g_embnb[(size_t)NEMB * KDIM];
__device__ int                          g_cand[(size_t)MROWS * CAND_CAP];
__device__ int                          g_ccnt[MROWS];
__device__ int                          g_idx[MROWS];

// ---------------- row L2 normalize: emb -> g_embn / g_embnb -----------------
__global__ void norm_emb_kernel(const float* __restrict__ emb) {
    int row = blockIdx.x;
    int t = threadIdx.x;   // 128 threads, 512 floats per row
    float4 v = reinterpret_cast<const float4*>(emb + (size_t)row * KDIM)[t];
    float ss = v.x*v.x + v.y*v.y + v.z*v.z + v.w*v.w;
    #pragma unroll
    for (int o = 16; o > 0; o >>= 1) ss += __shfl_xor_sync(0xffffffffu, ss, o);
    __shared__ float ws[4];
    if ((t & 31) == 0) ws[t >> 5] = ss;
    __syncthreads();
    float s = 1.0f / fmaxf(sqrtf(ws[0] + ws[1] + ws[2] + ws[3]), 1e-12f);
    float4 o4 = make_float4(v.x*s, v.y*s, v.z*s, v.w*s);
    reinterpret_cast<float4*>(g_embn + (size_t)row * KDIM)[t] = o4;
    __nv_bfloat162* ob = reinterpret_cast<__nv_bfloat162*>(g_embnb + (size_t)row * KDIM);
    ob[t*2]     = __floats2bfloat162_rn(o4.x, o4.y);
    ob[t*2 + 1] = __floats2bfloat162_rn(o4.z, o4.w);
}

// ---------------- row L2 normalize: g_zf (in place) -> g_zfb ----------------
__global__ void norm_zf_kernel() {
    int row = blockIdx.x;
    int t = threadIdx.x;
    float4 v = reinterpret_cast<const float4*>(g_zf + (size_t)row * KDIM)[t];
    float ss = v.x*v.x + v.y*v.y + v.z*v.z + v.w*v.w;
    #pragma unroll
    for (int o = 16; o > 0; o >>= 1) ss += __shfl_xor_sync(0xffffffffu, ss, o);
    __shared__ float ws[4];
    if ((t & 31) == 0) ws[t >> 5] = ss;
    __syncthreads();
    float s = 1.0f / fmaxf(sqrtf(ws[0] + ws[1] + ws[2] + ws[3]), 1e-12f);
    float4 o4 = make_float4(v.x*s, v.y*s, v.z*s, v.w*s);
    reinterpret_cast<float4*>(g_zf + (size_t)row * KDIM)[t] = o4;
    __nv_bfloat162* ob = reinterpret_cast<__nv_bfloat162*>(g_zfb + (size_t)row * KDIM);
    ob[t*2]     = __floats2bfloat162_rn(o4.x, o4.y);
    ob[t*2 + 1] = __floats2bfloat162_rn(o4.z, o4.w);
}

// ---------------- fp32 SGEMM: C[m][n] = sum_k A[m][k]*B[n][k] + bias[n] -----
// GATHER=false: A = Aext (z),           C = g_zf
// GATHER=true : A = g_embn[g_idx[m]],   C = Cext (d_out)
template<bool GATHER>
__global__ void __launch_bounds__(256) sgemm512(const float* __restrict__ Aext,
                                                const float* __restrict__ Bw,
                                                const float* __restrict__ bias,
                                                float* __restrict__ Cext) {
    constexpr int BM = 128, BN = 128, BK = 16;
    __shared__ float As[BK][BM];
    __shared__ float Bs[BK][BN];
    const int tid = threadIdx.x;
    const int tx = tid & 15, ty = tid >> 4;
    const int m0 = blockIdx.y * BM, n0 = blockIdx.x * BN;
    const int lr = tid >> 1;          // 0..127 (tile row loaded by this thread)
    const int lc = (tid & 1) << 3;    // 0 or 8 (k offset)
    const float* Arow;
    if (GATHER) Arow = g_embn + (size_t)g_idx[m0 + lr] * KDIM;
    else        Arow = Aext + (size_t)(m0 + lr) * KDIM;
    const float* Brow = Bw + (size_t)(n0 + lr) * KDIM;
    float* C = GATHER ? Cext : g_zf;

    float acc[8][8];
    #pragma unroll
    for (int i = 0; i < 8; ++i)
        #pragma unroll
        for (int j = 0; j < 8; ++j) acc[i][j] = 0.0f;

    for (int k0 = 0; k0 < KDIM; k0 += BK) {
        float4 a0 = *reinterpret_cast<const float4*>(Arow + k0 + lc);
        float4 a1 = *reinterpret_cast<const float4*>(Arow + k0 + lc + 4);
        float4 b0 = *reinterpret_cast<const float4*>(Brow + k0 + lc);
        float4 b1 = *reinterpret_cast<const float4*>(Brow + k0 + lc + 4);
        As[lc+0][lr] = a0.x; As[lc+1][lr] = a0.y; As[lc+2][lr] = a0.z; As[lc+3][lr] = a0.w;
        As[lc+4][lr] = a1.x; As[lc+5][lr] = a1.y; As[lc+6][lr] = a1.z; As[lc+7][lr] = a1.w;
        Bs[lc+0][lr] = b0.x; Bs[lc+1][lr] = b0.y; Bs[lc+2][lr] = b0.z; Bs[lc+3][lr] = b0.w;
        Bs[lc+4][lr] = b1.x; Bs[lc+5][lr] = b1.y; Bs[lc+6][lr] = b1.z; Bs[lc+7][lr] = b1.w;
        __syncthreads();
        #pragma unroll
        for (int kk = 0; kk < BK; ++kk) {
            float a[8], b[8];
            *reinterpret_cast<float4*>(a)     = *reinterpret_cast<const float4*>(&As[kk][ty*8]);
            *reinterpret_cast<float4*>(a + 4) = *reinterpret_cast<const float4*>(&As[kk][ty*8 + 4]);
            *reinterpret_cast<float4*>(b)     = *reinterpret_cast<const float4*>(&Bs[kk][tx*8]);
            *reinterpret_cast<float4*>(b + 4) = *reinterpret_cast<const float4*>(&Bs[kk][tx*8 + 4]);
            #pragma unroll
            for (int i = 0; i < 8; ++i)
                #pragma unroll
                for (int j = 0; j < 8; ++j) acc[i][j] += a[i] * b[j];
        }
        __syncthreads();
    }

    float bb[8];
    *reinterpret_cast<float4*>(bb)     = *reinterpret_cast<const float4*>(bias + n0 + tx*8);
    *reinterpret_cast<float4*>(bb + 4) = *reinterpret_cast<const float4*>(bias + n0 + tx*8 + 4);
    #pragma unroll
    for (int i = 0; i < 8; ++i) {
        int m = m0 + ty*8 + i;
        float* cp = C + (size_t)m * KDIM + n0 + tx*8;
        *reinterpret_cast<float4*>(cp) =
            make_float4(acc[i][0]+bb[0], acc[i][1]+bb[1], acc[i][2]+bb[2], acc[i][3]+bb[3]);
        *reinterpret_cast<float4*>(cp + 4) =
            make_float4(acc[i][4]+bb[4], acc[i][5]+bb[5], acc[i][6]+bb[6], acc[i][7]+bb[7]);
    }
}

// ---------------- bf16 mma.sync m16n8k16 helper -----------------------------
__device__ __forceinline__ void mma_bf16(float* c, const unsigned* a, const unsigned* b) {
    asm volatile(
        "mma.sync.aligned.m16n8k16.row.col.f32.bf16.bf16.f32 "
        "{%0,%1,%2,%3}, {%4,%5,%6,%7}, {%8,%9}, {%0,%1,%2,%3};\n"
        : "+f"(c[0]), "+f"(c[1]), "+f"(c[2]), "+f"(c[3])
        : "r"(a[0]), "r"(a[1]), "r"(a[2]), "r"(a[3]), "r"(b[0]), "r"(b[1]));
}

// ---------------- distance GEMM (bf16) + candidate collection ---------------
// Block: 64 zf rows vs all 8192 codes in 64-code tiles. Per row, keep every
// code within eps of the running max (superset of the fp32 argmax).
__global__ void __launch_bounds__(256) dist_cand_kernel() {
    constexpr int BM = 64, BN = 64, BK = 64, LDSB = 72; // padded k-stride (bf16 elems)
    __shared__ __align__(16) unsigned char sraw[(BM + BN) * LDSB * 2]; // 18432B
    __nv_bfloat16* As = reinterpret_cast<__nv_bfloat16*>(sraw);
    __nv_bfloat16* Bs = As + BM * LDSB;
    float* Ss = reinterpret_cast<float*>(sraw); // [64][65] overlay, 16640B

    const int tid = threadIdx.x;
    const int lane = tid & 31, wid = tid >> 5;
    const int g = lane >> 2, tg = lane & 3;
    const int wm = (wid & 1) * 32;   // warp row base (2 warps in m)
    const int wn = (wid >> 1) * 16;  // warp col base (4 warps in n)
    const int m0 = blockIdx.x * BM;

    float best = -3.4e38f;
    int cnt = 0;

    for (int nt = 0; nt < NEMB / BN; ++nt) {
        float acc[2][2][4];
        #pragma unroll
        for (int i = 0; i < 2; ++i)
            #pragma unroll
            for (int j = 0; j < 2; ++j)
                #pragma unroll
                for (int q = 0; q < 4; ++q) acc[i][j][q] = 0.0f;

        for (int kt = 0; kt < KDIM / BK; ++kt) {
            #pragma unroll
            for (int i = 0; i < 2; ++i) {
                int vec = tid + i * 256;
                int r = vec >> 3;
                int vc = (vec & 7) << 3;
                *reinterpret_cast<uint4*>(As + r * LDSB + vc) =
                    *reinterpret_cast<const uint4*>(g_zfb + (size_t)(m0 + r) * KDIM + kt * BK + vc);
                *reinterpret_cast<uint4*>(Bs + r * LDSB + vc) =
                    *reinterpret_cast<const uint4*>(g_embnb + (size_t)(nt * BN + r) * KDIM + kt * BK + vc);
            }
            __syncthreads();
            #pragma unroll
            for (int kk = 0; kk < BK; kk += 16) {
                unsigned a[2][4], b[2][2];
                #pragma unroll
                for (int ms = 0; ms < 2; ++ms) {
                    const __nv_bfloat16* p = As + (wm + ms*16 + g) * LDSB + kk + tg*2;
                    a[ms][0] = *reinterpret_cast<const unsigned*>(p);
                    a[ms][1] = *reinterpret_cast<const unsigned*>(p + 8*LDSB);
                    a[ms][2] = *reinterpret_cast<const unsigned*>(p + 8);
                    a[ms][3] = *reinterpret_cast<const unsigned*>(p + 8*LDSB + 8);
                }
                #pragma unroll
                for (int ns = 0; ns < 2; ++ns) {
                    const __nv_bfloat16* q = Bs + (wn + ns*8 + g) * LDSB + kk + tg*2;
                    b[ns][0] = *reinterpret_cast<const unsigned*>(q);
                    b[ns][1] = *reinterpret_cast<const unsigned*>(q + 8);
                }
                #pragma unroll
                for (int ms = 0; ms < 2; ++ms)
                    #pragma unroll
                    for (int ns = 0; ns < 2; ++ns)
                        mma_bf16(acc[ms][ns], a[ms], b[ns]);
            }
            __syncthreads();
        }
        // stage scores to shared (overlays As/Bs; all tile reads are done)
        #pragma unroll
        for (int ms = 0; ms < 2; ++ms)
            #pragma unroll
            for (int ns = 0; ns < 2; ++ns) {
                int r = wm + ms*16 + g;
                int c = wn + ns*8 + tg*2;
                Ss[r*65 + c]         = acc[ms][ns][0];
                Ss[r*65 + c + 1]     = acc[ms][ns][1];
                Ss[(r+8)*65 + c]     = acc[ms][ns][2];
                Ss[(r+8)*65 + c + 1] = acc[ms][ns][3];
            }
        __syncthreads();
        if (tid < BM) {
            #pragma unroll 1
            for (int c = 0; c < BN; ++c) {
                float v = Ss[tid*65 + c];
                if (v > best - 4e-3f) {   // eps ~ 23 sigma of bf16 dot error
                    if (cnt < CAND_CAP)
                        g_cand[(size_t)(m0 + tid) * CAND_CAP + cnt] = nt * BN + c;
                    ++cnt;
                    if (v > best) best = v;
                }
            }
        }
        __syncthreads();
    }
    if (tid < BM) g_ccnt[m0 + tid] = cnt;
}

// ---------------- exact fp32 rescore of candidates -> argmax index ----------
__global__ void __launch_bounds__(256) rescore_kernel() {
    int wid = threadIdx.x >> 5;
    int lane = threadIdx.x & 31;
    int row = blockIdx.x * 8 + wid;
    const float* zr = g_zf + (size_t)row * KDIM;
    float zv[16];
    #pragma unroll
    for (int i = 0; i < 16; ++i) zv[i] = zr[lane + 32*i];
    int cnt = g_ccnt[row];
    float best = -3.4e38f;
    int bi = 0;
    if (cnt <= CAND_CAP) {
        for (int c = 0; c < cnt; ++c) {   // ascending code order
            int code = g_cand[(size_t)row * CAND_CAP + c];
            const float* er = g_embn + (size_t)code * KDIM;
            float s = 0.0f;
            #pragma unroll
            for (int i = 0; i < 16; ++i) s += zv[i] * er[lane + 32*i];
            #pragma unroll
            for (int o = 16; o > 0; o >>= 1) s += __shfl_xor_sync(0xffffffffu, s, o);
            if (s > best) { best = s; bi = code; }  // strict > => first max
        }
    } else {
        // overflow fallback: full fp32 scan (statistically never)
        for (int code = 0; code < NEMB; ++code) {
            const float* er = g_embn + (size_t)code * KDIM;
            float s = 0.0f;
            #pragma unroll
            for (int i = 0; i < 16; ++i) s += zv[i] * er[lane + 32*i];
            #pragma unroll
            for (int o = 16; o > 0; o >>= 1) s += __shfl_xor_sync(0xffffffffu, s, o);
            if (s > best) { best = s; bi = code; }
        }
    }
    if (lane == 0) g_idx[row] = bi;
}

// ---------------- write idx (cast to float) to output tail ------------------
__global__ void write_idx_kernel(float* __restrict__ dst, int n) {
    int i = blockIdx.x * blockDim.x + threadIdx.x;
    if (i < n) dst[i] = (float)g_idx[i];
}

// ---------------- launch ----------------------------------------------------
extern "C" void kernel_launch(void* const* d_in, const int* in_sizes, int n_in,
                              void* d_out, int out_size) {
    const float* z     = (const float*)d_in[0];
    // d_in[1] = mask (all true; unused by the reference math)
    const float* W_in  = (const float*)d_in[2];
    const float* b_in  = (const float*)d_in[3];
    const float* W_out = (const float*)d_in[4];
    const float* b_out = (const float*)d_in[5];
    const float* emb   = (const float*)d_in[6];
    float* out = (float*)d_out;

    // 1) normalize embedding table (fp32 + bf16 copies)
    norm_emb_kernel<<<NEMB, 128>>>(emb);
    // 2) zf = z @ W_in^T + b_in   (fp32, into g_zf)
    sgemm512<false><<<dim3(KDIM/128, MROWS/128), 256>>>(z, W_in, b_in, nullptr);
    // 3) normalize zf rows (fp32 in place + bf16 copy)
    norm_zf_kernel<<<MROWS, 128>>>();
    // 4) bf16 similarity GEMM + candidate collection
    dist_cand_kernel<<<MROWS/64, 256>>>();
    // 5) exact fp32 rescore -> g_idx
    rescore_kernel<<<MROWS/8, 256>>>();
    // 6) out = emb_n[idx] @ W_out^T + b_out  (straight-through forward value)
    sgemm512<true><<<dim3(KDIM/128, MROWS/128), 256>>>(nullptr, W_out, b_out, out);
    // 7) idx tail (cast to output dtype) if the output buffer carries it
    int tail = out_size - MROWS * KDIM;
    if (tail > 0) {
        int n = tail < MROWS ? tail : MROWS;
        write_idx_kernel<<<(n + 255) / 256, 256>>>(out + (size_t)MROWS * KDIM, n);
    }
}